// round 12
// baseline (speedup 1.0000x reference)
#include <cuda_runtime.h>
#include <cuda_fp16.h>
#include <math.h>
#include <stdint.h>

// Problem constants
#define NN 30000      // nodes
#define EE 150000     // edges per graph
#define IND 512
#define HIDD 512
#define OUTD 256
#define GG 3
#define CONCAT (HIDD * GG)   // 1536

// ============================================================================
// Scratch (device globals)
// ============================================================================
__device__ __half g_X16[(size_t)NN * IND];        // x in fp16
__device__ __half g_AX[(size_t)GG * NN * IND];    // aggregated, scaled X (fp16)
__device__ __half g_H [(size_t)NN * CONCAT];      // tanh(...) (fp16)
__device__ __half g_Bt [(size_t)CONCAT * IND];    // [W0|W1|W2]^T : row n, col k (fp16)
__device__ __half g_BtL[(size_t)OUTD * CONCAT];   // W_lin^T : row n, col k (fp16)
__device__ int   g_deg[2 * GG * NN];              // [0,GG*NN)=deg_in, rest deg_out
__device__ int   g_off    [GG * (NN + 1)];
__device__ int   g_cursor [GG * NN];
__device__ int   g_csr_src[GG * EE];
__device__ float g_alpha  [GG];

#define DEG_IN(g, i)  g_deg[(g) * NN + (i)]
#define DEG_OUT(g, i) g_deg[GG * NN + (g) * NN + (i)]

// ============================================================================
// PTX helpers (plain-sm_103-legal: cp.async / ldmatrix / mma.sync)
// ============================================================================
__device__ __forceinline__ uint32_t smem_to_u32(const void* p) {
    uint32_t a;
    asm("{ .reg .u64 t; cvta.to.shared.u64 t, %1; cvt.u32.u64 %0, t; }" : "=r"(a) : "l"(p));
    return a;
}
#define CP16(dst32, src) \
    asm volatile("cp.async.cg.shared.global [%0], [%1], 16;" :: "r"(dst32), "l"(src))
#define CP_COMMIT() asm volatile("cp.async.commit_group;" ::: "memory")
#define CP_WAIT(n)  asm volatile("cp.async.wait_group %0;" :: "n"(n) : "memory")

#define LDSM_X4(r0, r1, r2, r3, addr) \
    asm volatile("ldmatrix.sync.aligned.m8n8.x4.shared.b16 {%0,%1,%2,%3}, [%4];" \
        : "=r"(r0), "=r"(r1), "=r"(r2), "=r"(r3) : "r"(addr))

#define MMA_F16(c, a, b) \
    asm volatile("mma.sync.aligned.m16n8k16.row.col.f32.f16.f16.f32 " \
        "{%0,%1,%2,%3}, {%4,%5,%6,%7}, {%8,%9}, {%0,%1,%2,%3};" \
        : "+f"((c)[0]), "+f"((c)[1]), "+f"((c)[2]), "+f"((c)[3]) \
        : "r"((a)[0]), "r"((a)[1]), "r"((a)[2]), "r"((a)[3]), "r"((b)[0]), "r"((b)[1]))

// fast tanh: 1 - 2/(exp(2x)+1); rel err ~1e-6
__device__ __forceinline__ float fast_tanh(float x) {
    float e = __expf(2.0f * x);
    return 1.0f - __fdividef(2.0f, e + 1.0f);
}

// ============================================================================
// Setup kernels
// ============================================================================
__global__ void hist_kernel(const int* __restrict__ e0, const int* __restrict__ e1,
                            const int* __restrict__ e2) {
    int i = blockIdx.x * blockDim.x + threadIdx.x;
    if (i >= GG * EE) return;
    int g = i / EE, idx = i - g * EE;
    const int* e = (g == 0) ? e0 : (g == 1) ? e1 : e2;
    atomicAdd(&DEG_OUT(g, e[idx]), 1);
    atomicAdd(&DEG_IN (g, e[EE + idx]), 1);
}

#define SCHUNK 30   // 1024*30 = 30720 >= NN
__global__ void scan_kernel(const float* __restrict__ alphas) {
    int g = blockIdx.x;
    if (g == 0 && threadIdx.x == 0) {
        float m = alphas[0];
        for (int i = 1; i < GG; i++) m = fmaxf(m, alphas[i]);
        float s = 0.f, e[GG];
        for (int i = 0; i < GG; i++) { e[i] = expf(alphas[i] - m); s += e[i]; }
        for (int i = 0; i < GG; i++) g_alpha[i] = e[i] / s;
    }
    const int* cnt = &DEG_IN(g, 0);
    int* off = g_off + g * (NN + 1);
    int* cur = g_cursor + g * NN;
    __shared__ int sh[1024];
    int t = threadIdx.x;
    int base = t * SCHUNK;

    int s = 0;
    #pragma unroll 5
    for (int j = 0; j < SCHUNK; j++) {
        int i = base + j;
        s += (i < NN) ? cnt[i] : 0;
    }
    sh[t] = s;
    __syncthreads();
    #pragma unroll
    for (int st = 1; st < 1024; st <<= 1) {
        int v = (t >= st) ? sh[t - st] : 0;
        __syncthreads();
        sh[t] += v;
        __syncthreads();
    }
    int run = sh[t] - s;
    #pragma unroll 5
    for (int j = 0; j < SCHUNK; j++) {
        int i = base + j;
        if (i < NN) {
            off[i] = run; cur[i] = run;
            run += cnt[i];
        }
    }
    if (t == 1023) off[NN] = sh[1023];
}

__global__ void fill_kernel(const int* __restrict__ e0, const int* __restrict__ e1,
                            const int* __restrict__ e2) {
    int i = blockIdx.x * blockDim.x + threadIdx.x;
    if (i >= GG * EE) return;
    int g = i / EE, idx = i - g * EE;
    const int* e = (g == 0) ? e0 : (g == 1) ? e1 : e2;
    int src = e[idx];
    int dst = e[EE + idx];
    int p = atomicAdd(&g_cursor[g * NN + dst], 1);
    g_csr_src[g * EE + p] = src;
}

// ============================================================================
// Merged conversion (vectorized)
// ============================================================================
#define CX4_TOTAL  (NN * IND / 4)
#define CW_TOTAL   (GG * IND * HIDD)
#define CWL_TOTAL  (CONCAT * OUTD)
#define CONV_TOTAL (CX4_TOTAL + CW_TOTAL + CWL_TOTAL)

__global__ void conv_all_kernel(const float* __restrict__ x,
                                const float* __restrict__ W0,
                                const float* __restrict__ W1,
                                const float* __restrict__ W2,
                                const float* __restrict__ WL) {
    int i = blockIdx.x * blockDim.x + threadIdx.x;
    const float4* x4 = (const float4*)x;
    __half2* X2 = (__half2*)g_X16;
    for (int idx = i; idx < CONV_TOTAL; idx += gridDim.x * blockDim.x) {
        if (idx < CX4_TOTAL) {
            float4 v = x4[idx];
            X2[idx * 2]     = __floats2half2_rn(v.x, v.y);
            X2[idx * 2 + 1] = __floats2half2_rn(v.z, v.w);
        } else if (idx < CX4_TOTAL + CW_TOTAL) {
            int t = idx - CX4_TOTAL;
            int k = t & 511;
            int n = (t >> 9) & 511;
            int g = t >> 18;
            const float* W = (g == 0) ? W0 : (g == 1) ? W1 : W2;
            g_Bt[(size_t)(g * HIDD + n) * IND + k] = __float2half(W[k * HIDD + n]);
        } else {
            int t = idx - CX4_TOTAL - CW_TOTAL;
            int k = t % CONCAT;
            int n = t / CONCAT;
            g_BtL[(size_t)n * CONCAT + k] = __float2half(WL[k * OUTD + n]);
        }
    }
}

// ============================================================================
// Pre-GEMM aggregation on fp16 X (fp32 accum, fp16 out), ONE graph per launch.
// Edge loop unrolled x2 with dual accumulators for MLP.
// ============================================================================
__global__ void __launch_bounds__(128)
agg_x_kernel(int g) {
    int dst = blockIdx.x;
    int c = threadIdx.x * 4;

    int beg = g_off[g * (NN + 1) + dst];
    int end = g_off[g * (NN + 1) + dst + 1];
    const int* srcs = g_csr_src + g * EE;
    const int* dout = &DEG_OUT(g, 0);

    float4 acc0 = make_float4(0.f, 0.f, 0.f, 0.f);
    float4 acc1 = make_float4(0.f, 0.f, 0.f, 0.f);
    int e = beg;
    for (; e + 1 < end; e += 2) {
        int s0 = srcs[e], s1 = srcs[e + 1];
        int d0 = dout[s0], d1 = dout[s1];
        float so0 = rsqrtf((float)(d0 > 1 ? d0 : 1));
        float so1 = rsqrtf((float)(d1 > 1 ? d1 : 1));
        const __half2* x0 = (const __half2*)(g_X16 + (size_t)s0 * IND + c);
        const __half2* x1 = (const __half2*)(g_X16 + (size_t)s1 * IND + c);
        __half2 a01 = x0[0], a23 = x0[1];
        __half2 b01 = x1[0], b23 = x1[1];
        float2 fa01 = __half22float2(a01), fa23 = __half22float2(a23);
        float2 fb01 = __half22float2(b01), fb23 = __half22float2(b23);
        acc0.x += fa01.x * so0; acc0.y += fa01.y * so0;
        acc0.z += fa23.x * so0; acc0.w += fa23.y * so0;
        acc1.x += fb01.x * so1; acc1.y += fb01.y * so1;
        acc1.z += fb23.x * so1; acc1.w += fb23.y * so1;
    }
    if (e < end) {
        int s0 = srcs[e];
        int d0 = dout[s0];
        float so0 = rsqrtf((float)(d0 > 1 ? d0 : 1));
        const __half2* x0 = (const __half2*)(g_X16 + (size_t)s0 * IND + c);
        __half2 a01 = x0[0], a23 = x0[1];
        float2 fa01 = __half22float2(a01), fa23 = __half22float2(a23);
        acc0.x += fa01.x * so0; acc0.y += fa01.y * so0;
        acc0.z += fa23.x * so0; acc0.w += fa23.y * so0;
    }
    acc0.x += acc1.x; acc0.y += acc1.y; acc0.z += acc1.z; acc0.w += acc1.w;

    int di = DEG_IN(g, dst);
    float rsv = rsqrtf((float)(di > 1 ? di : 1));

    size_t base = ((size_t)g * NN + dst) * IND + c;
    *(__half2*)(g_AX + base)     = __halves2half2(__float2half(acc0.x * rsv),
                                                  __float2half(acc0.y * rsv));
    *(__half2*)(g_AX + base + 2) = __halves2half2(__float2half(acc0.z * rsv),
                                                  __float2half(acc0.w * rsv));
}

// ============================================================================
// Single-pass fp16 GEMM: 128 threads, 4 warps (2x2), warp tile (BM/2) x 64.
// CTA tile BM x 128, BK=64, 3-stage cp.async pipeline, 1 barrier/chunk,
// swizzled ldmatrix, 2 CTAs/SM.
// mode 1: fixed g arg; A=g_AX[g] (K=512), B=g_Bt[g]; tanh -> g_H
// mode 2: A=g_H (K=1536), B=g_BtL; +bias -> outp
// ============================================================================
#define NSTAGE 3

template<int BM>
__device__ __forceinline__ void prefetch_chunk(uint32_t sdst,
        const __half* __restrict__ A, const __half* __restrict__ B,
        int kc, int m0, int n0, int K, int tid) {
    const int TOT = (BM + 128) * 8;   // 16B segments
    #pragma unroll
    for (int i = tid; i < TOT; i += 128) {
        int row = i >> 3;
        int col = (i & 7) * 16;
        if (row < BM) {
            int mrow = m0 + row; if (mrow >= NN) mrow = NN - 1;  // clamped rows never stored
            uint32_t swz = ((uint32_t)(row * 128 + col)) ^ ((uint32_t)(row & 7) << 4);
            CP16(sdst + swz, (const char*)(A + (size_t)mrow * K) + kc * 128 + col);
        } else {
            int r2 = row - BM;
            uint32_t swz = ((uint32_t)(r2 * 128 + col)) ^ ((uint32_t)(r2 & 7) << 4);
            CP16(sdst + BM * 128 + swz, (const char*)(B + (size_t)(n0 + r2) * K) + kc * 128 + col);
        }
    }
}

template<int BM, int MI>
__global__ void __launch_bounds__(128, 2)
mma_gemm_kernel(float* outp, const float* __restrict__ bias,
                int mode, int K, int g) {
    constexpr int SBYTES = (BM + 128) * 128;
    extern __shared__ char smem_raw[];
    uint32_t sb0 = smem_to_u32(smem_raw);
    uint32_t sb = (sb0 + 1023) & ~1023u;

    const __half *A, *B;
    if (mode == 1) {
        A = g_AX + (size_t)g * NN * IND;
        B = g_Bt + (size_t)g * HIDD * IND;
    } else {
        A = g_H; B = g_BtL;
    }

    int tid = threadIdx.x;
    int lane = tid & 31, wid = tid >> 5;
    int warpM = wid >> 1, warpN = wid & 1;     // 2x2 warp grid
    int n0 = blockIdx.x * 128;
    int m0 = blockIdx.y * BM;

    float acc[MI][8][4];
    #pragma unroll
    for (int i = 0; i < MI; i++)
        #pragma unroll
        for (int j = 0; j < 8; j++)
            #pragma unroll
            for (int r = 0; r < 4; r++) acc[i][j][r] = 0.f;

    int aRow = warpM * (BM / 2) + (lane & 15);
    int aCol = (lane >> 4) * 16;
    int bRow = warpN * 64 + (lane & 7) + (lane >> 4) * 8;
    int bCol = ((lane >> 3) & 1) * 16;

    int nk = K >> 6;
    prefetch_chunk<BM>(sb, A, B, 0, m0, n0, K, tid);
    CP_COMMIT();
    if (nk > 1) { prefetch_chunk<BM>(sb + SBYTES, A, B, 1, m0, n0, K, tid); }
    CP_COMMIT();

    for (int kc = 0; kc < nk; kc++) {
        if (kc + 2 < nk) CP_WAIT(1);
        else             CP_WAIT(0);
        __syncthreads();
        if (kc + 2 < nk) {
            prefetch_chunk<BM>(sb + ((kc + 2) % NSTAGE) * SBYTES, A, B, kc + 2, m0, n0, K, tid);
            CP_COMMIT();
        }

        uint32_t abase = sb + (kc % NSTAGE) * SBYTES;
        uint32_t bbase = abase + BM * 128;

        #pragma unroll
        for (int q = 0; q < 4; q++) {
            uint32_t bh[4][4];
            #pragma unroll
            for (int gi = 0; gi < 4; gi++) {
                int r = bRow + gi * 16;
                uint32_t off = ((uint32_t)(r * 128 + q * 32 + bCol)) ^ ((uint32_t)(r & 7) << 4);
                LDSM_X4(bh[gi][0], bh[gi][1], bh[gi][2], bh[gi][3], bbase + off);
            }
            #pragma unroll
            for (int mi = 0; mi < MI; mi++) {
                int r = aRow + mi * 16;
                uint32_t off = ((uint32_t)(r * 128 + q * 32 + aCol)) ^ ((uint32_t)(r & 7) << 4);
                uint32_t ah[4];
                LDSM_X4(ah[0], ah[1], ah[2], ah[3], abase + off);
                #pragma unroll
                for (int nj = 0; nj < 8; nj++) {
                    uint32_t bf[2] = { bh[nj >> 1][(nj & 1) * 2], bh[nj >> 1][(nj & 1) * 2 + 1] };
                    MMA_F16(acc[mi][nj], ah, bf);
                }
            }
        }
    }

    float alpha = (mode == 1) ? g_alpha[g] : 0.f;

    #pragma unroll
    for (int mi = 0; mi < MI; mi++) {
        #pragma unroll
        for (int nj = 0; nj < 8; nj++) {
            int m = m0 + warpM * (BM / 2) + mi * 16 + (lane >> 2);
            int n = n0 + warpN * 64 + nj * 8 + (lane & 3) * 2;
            float c0 = acc[mi][nj][0], c1 = acc[mi][nj][1];
            float c2 = acc[mi][nj][2], c3 = acc[mi][nj][3];
            float bx = bias[n], by = bias[n + 1];
            if (mode == 1) {
                size_t coln = (size_t)g * HIDD + n;
                if (m < NN) {
                    float h0 = fast_tanh(alpha * (c0 + bx));
                    float h1 = fast_tanh(alpha * (c1 + by));
                    *(__half2*)(g_H + (size_t)m * CONCAT + coln) =
                        __halves2half2(__float2half(h0), __float2half(h1));
                }
                if (m + 8 < NN) {
                    float h2 = fast_tanh(alpha * (c2 + bx));
                    float h3 = fast_tanh(alpha * (c3 + by));
                    *(__half2*)(g_H + (size_t)(m + 8) * CONCAT + coln) =
                        __halves2half2(__float2half(h2), __float2half(h3));
                }
            } else {
                if (m < NN)
                    *(float2*)(outp + (size_t)m * OUTD + n) = make_float2(c0 + bx, c1 + by);
                if (m + 8 < NN)
                    *(float2*)(outp + (size_t)(m + 8) * OUTD + n) = make_float2(c2 + bx, c3 + by);
            }
        }
    }
}

#define SMEM1 (1024 + NSTAGE * (128 + 128) * 128)   // 99328
#define SMEM2 (1024 + NSTAGE * (64 + 128) * 128)    // 74752

// ============================================================================
// Launch — per-graph agg/GEMM1 pipelined across streams.
// ============================================================================
extern "C" void kernel_launch(void* const* d_in, const int* in_sizes, int n_in,
                              void* d_out, int out_size) {
    const float* x = nullptr;
    const int*   e[GG]  = {nullptr, nullptr, nullptr};
    const float* W[GG]  = {nullptr, nullptr, nullptr};
    const float* b[GG]  = {nullptr, nullptr, nullptr};
    const float* alphas = nullptr;
    const float* W_lin  = nullptr;
    const float* b_lin  = nullptr;
    int ne = 0, nw = 0, nb = 0;

    for (int i = 0; i < n_in; i++) {
        int sz = in_sizes[i];
        if      (sz == NN * IND)      x = (const float*)d_in[i];
        else if (sz == 2 * EE)        { if (ne < GG) e[ne++] = (const int*)d_in[i]; }
        else if (sz == IND * HIDD)    { if (nw < GG) W[nw++] = (const float*)d_in[i]; }
        else if (sz == HIDD)          { if (nb < GG) b[nb++] = (const float*)d_in[i]; }
        else if (sz == GG)            alphas = (const float*)d_in[i];
        else if (sz == CONCAT * OUTD) W_lin = (const float*)d_in[i];
        else if (sz == OUTD)          b_lin = (const float*)d_in[i];
    }
    float* out = (float*)d_out;

    static cudaStream_t s2 = nullptr, s3 = nullptr;
    static cudaEvent_t ev_fork = nullptr, ev_conv = nullptr, ev_csr = nullptr;
    static cudaEvent_t ev_agg[GG] = {nullptr, nullptr, nullptr};
    if (!s2) {
        cudaStreamCreateWithFlags(&s2, cudaStreamNonBlocking);
        cudaStreamCreateWithFlags(&s3, cudaStreamNonBlocking);
        cudaEventCreateWithFlags(&ev_fork, cudaEventDisableTiming);
        cudaEventCreateWithFlags(&ev_conv, cudaEventDisableTiming);
        cudaEventCreateWithFlags(&ev_csr, cudaEventDisableTiming);
        for (int g = 0; g < GG; g++)
            cudaEventCreateWithFlags(&ev_agg[g], cudaEventDisableTiming);
    }

    cudaFuncSetAttribute((const void*)mma_gemm_kernel<128, 4>,
                         cudaFuncAttributeMaxDynamicSharedMemorySize, SMEM1);
    cudaFuncSetAttribute((const void*)mma_gemm_kernel<64, 2>,
                         cudaFuncAttributeMaxDynamicSharedMemorySize, SMEM2);

    void* degp = nullptr;
    cudaGetSymbolAddress(&degp, g_deg);
    cudaMemsetAsync(degp, 0, sizeof(int) * 2 * GG * NN, 0);

    // Fork conv onto s2 to overlap with CSR build on s0
    cudaEventRecord(ev_fork, 0);
    cudaStreamWaitEvent(s2, ev_fork, 0);
    conv_all_kernel<<<1184, 256, 0, s2>>>(x, W[0], W[1], W[2], W_lin);
    cudaEventRecord(ev_conv, s2);

    hist_kernel<<<(GG * EE + 255) / 256, 256>>>(e[0], e[1], e[2]);
    scan_kernel<<<GG, 1024>>>(alphas);
    fill_kernel<<<(GG * EE + 255) / 256, 256>>>(e[0], e[1], e[2]);
    cudaEventRecord(ev_csr, 0);

    // s3: per-graph aggregation chain (needs CSR + X16)
    cudaStreamWaitEvent(s3, ev_csr, 0);
    cudaStreamWaitEvent(s3, ev_conv, 0);
    for (int g = 0; g < GG; g++) {
        agg_x_kernel<<<NN, 128, 0, s3>>>(g);
        cudaEventRecord(ev_agg[g], s3);
    }

    // s0: per-graph GEMM1 pipelined against agg chain (ev_agg[g] covers conv too)
    int mtiles1 = (NN + 127) / 128;          // 235
    for (int g = 0; g < GG; g++) {
        cudaStreamWaitEvent(0, ev_agg[g], 0);
        dim3 grid1(HIDD / 128, mtiles1, 1);  // 4 x 235
        mma_gemm_kernel<128, 4><<<grid1, 128, SMEM1>>>(nullptr, b[g], 1, IND, g);
    }

    // GEMM2 after all of H is written (same stream, ordered)
    int mtiles2 = (NN + 63) / 64;            // 469
    dim3 grid2(OUTD / 128, mtiles2, 1);      // 2 x 469
    mma_gemm_kernel<64, 2><<<grid2, 128, SMEM2>>>(out, b_lin, 2, CONCAT, 0);
}

// round 13
// speedup vs baseline: 1.0909x; 1.0909x over previous
#include <cuda_runtime.h>
#include <cuda_fp16.h>
#include <math.h>
#include <stdint.h>

// Problem constants
#define NN 30000      // nodes
#define EE 150000     // edges per graph
#define IND 512
#define HIDD 512
#define OUTD 256
#define GG 3
#define CONCAT (HIDD * GG)   // 1536

// ============================================================================
// Scratch (device globals)
// ============================================================================
__device__ __half g_X16[(size_t)NN * IND];        // x in fp16
__device__ __half g_AX[(size_t)GG * NN * IND];    // aggregated, scaled X (fp16)
__device__ __half g_H [(size_t)NN * CONCAT];      // tanh(...) (fp16)
__device__ __half g_Bt [(size_t)CONCAT * IND];    // [W0|W1|W2]^T : row n, col k (fp16)
__device__ __half g_BtL[(size_t)OUTD * CONCAT];   // W_lin^T : row n, col k (fp16)
__device__ int   g_deg[2 * GG * NN];              // [0,GG*NN)=deg_in, rest deg_out
__device__ int   g_off    [GG * (NN + 1)];
__device__ int   g_cursor [GG * NN];
__device__ int   g_csr_src[GG * EE];
__device__ float g_alpha  [GG];

#define DEG_IN(g, i)  g_deg[(g) * NN + (i)]
#define DEG_OUT(g, i) g_deg[GG * NN + (g) * NN + (i)]

// ============================================================================
// PTX helpers (plain-sm_103-legal: cp.async / ldmatrix / mma.sync)
// ============================================================================
__device__ __forceinline__ uint32_t smem_to_u32(const void* p) {
    uint32_t a;
    asm("{ .reg .u64 t; cvta.to.shared.u64 t, %1; cvt.u32.u64 %0, t; }" : "=r"(a) : "l"(p));
    return a;
}
#define CP16(dst32, src) \
    asm volatile("cp.async.cg.shared.global [%0], [%1], 16;" :: "r"(dst32), "l"(src))
#define CP_COMMIT() asm volatile("cp.async.commit_group;" ::: "memory")
#define CP_WAIT(n)  asm volatile("cp.async.wait_group %0;" :: "n"(n) : "memory")

#define LDSM_X4(r0, r1, r2, r3, addr) \
    asm volatile("ldmatrix.sync.aligned.m8n8.x4.shared.b16 {%0,%1,%2,%3}, [%4];" \
        : "=r"(r0), "=r"(r1), "=r"(r2), "=r"(r3) : "r"(addr))

#define MMA_F16(c, a, b) \
    asm volatile("mma.sync.aligned.m16n8k16.row.col.f32.f16.f16.f32 " \
        "{%0,%1,%2,%3}, {%4,%5,%6,%7}, {%8,%9}, {%0,%1,%2,%3};" \
        : "+f"((c)[0]), "+f"((c)[1]), "+f"((c)[2]), "+f"((c)[3]) \
        : "r"((a)[0]), "r"((a)[1]), "r"((a)[2]), "r"((a)[3]), "r"((b)[0]), "r"((b)[1]))

// fast tanh: 1 - 2/(exp(2x)+1); rel err ~1e-6
__device__ __forceinline__ float fast_tanh(float x) {
    float e = __expf(2.0f * x);
    return 1.0f - __fdividef(2.0f, e + 1.0f);
}

// ============================================================================
// Setup kernels
// ============================================================================
__global__ void hist_kernel(const int* __restrict__ e0, const int* __restrict__ e1,
                            const int* __restrict__ e2) {
    int i = blockIdx.x * blockDim.x + threadIdx.x;
    if (i >= GG * EE) return;
    int g = i / EE, idx = i - g * EE;
    const int* e = (g == 0) ? e0 : (g == 1) ? e1 : e2;
    atomicAdd(&DEG_OUT(g, e[idx]), 1);
    atomicAdd(&DEG_IN (g, e[EE + idx]), 1);
}

#define SCHUNK 30   // 1024*30 = 30720 >= NN
__global__ void scan_kernel(const float* __restrict__ alphas) {
    int g = blockIdx.x;
    if (g == 0 && threadIdx.x == 0) {
        float m = alphas[0];
        for (int i = 1; i < GG; i++) m = fmaxf(m, alphas[i]);
        float s = 0.f, e[GG];
        for (int i = 0; i < GG; i++) { e[i] = expf(alphas[i] - m); s += e[i]; }
        for (int i = 0; i < GG; i++) g_alpha[i] = e[i] / s;
    }
    const int* cnt = &DEG_IN(g, 0);
    int* off = g_off + g * (NN + 1);
    int* cur = g_cursor + g * NN;
    __shared__ int sh[1024];
    int t = threadIdx.x;
    int base = t * SCHUNK;

    int s = 0;
    #pragma unroll 5
    for (int j = 0; j < SCHUNK; j++) {
        int i = base + j;
        s += (i < NN) ? cnt[i] : 0;
    }
    sh[t] = s;
    __syncthreads();
    #pragma unroll
    for (int st = 1; st < 1024; st <<= 1) {
        int v = (t >= st) ? sh[t - st] : 0;
        __syncthreads();
        sh[t] += v;
        __syncthreads();
    }
    int run = sh[t] - s;
    #pragma unroll 5
    for (int j = 0; j < SCHUNK; j++) {
        int i = base + j;
        if (i < NN) {
            off[i] = run; cur[i] = run;
            run += cnt[i];
        }
    }
    if (t == 1023) off[NN] = sh[1023];
}

__global__ void fill_kernel(const int* __restrict__ e0, const int* __restrict__ e1,
                            const int* __restrict__ e2) {
    int i = blockIdx.x * blockDim.x + threadIdx.x;
    if (i >= GG * EE) return;
    int g = i / EE, idx = i - g * EE;
    const int* e = (g == 0) ? e0 : (g == 1) ? e1 : e2;
    int src = e[idx];
    int dst = e[EE + idx];
    int p = atomicAdd(&g_cursor[g * NN + dst], 1);
    g_csr_src[g * EE + p] = src;
}

// ============================================================================
// Conversions, split by dependency: conv_x (needed by agg) / conv_w (by GEMM1/2)
// ============================================================================
__global__ void conv_x_kernel(const float* __restrict__ x) {
    int i = blockIdx.x * blockDim.x + threadIdx.x;
    const float4* x4 = (const float4*)x;
    __half2* X2 = (__half2*)g_X16;
    int total = NN * IND / 4;
    for (int idx = i; idx < total; idx += gridDim.x * blockDim.x) {
        float4 v = x4[idx];
        X2[idx * 2]     = __floats2half2_rn(v.x, v.y);
        X2[idx * 2 + 1] = __floats2half2_rn(v.z, v.w);
    }
}

#define CW_TOTAL   (GG * IND * HIDD)
#define CWL_TOTAL  (CONCAT * OUTD)
__global__ void conv_w_kernel(const float* __restrict__ W0,
                              const float* __restrict__ W1,
                              const float* __restrict__ W2,
                              const float* __restrict__ WL) {
    int i = blockIdx.x * blockDim.x + threadIdx.x;
    int total = CW_TOTAL + CWL_TOTAL;
    for (int idx = i; idx < total; idx += gridDim.x * blockDim.x) {
        if (idx < CW_TOTAL) {
            int k = idx & 511;
            int n = (idx >> 9) & 511;
            int g = idx >> 18;
            const float* W = (g == 0) ? W0 : (g == 1) ? W1 : W2;
            g_Bt[(size_t)(g * HIDD + n) * IND + k] = __float2half(W[k * HIDD + n]);
        } else {
            int t = idx - CW_TOTAL;
            int k = t % CONCAT;
            int n = t / CONCAT;
            g_BtL[(size_t)n * CONCAT + k] = __float2half(WL[k * OUTD + n]);
        }
    }
}

// ============================================================================
// Pre-GEMM aggregation on fp16 X (fp32 accum, fp16 out), grid (NN, GG),
// edge loop unrolled x2 with dual accumulators.
// ============================================================================
__global__ void __launch_bounds__(128)
agg_x_kernel() {
    int dst = blockIdx.x;
    int g = blockIdx.y;
    int c = threadIdx.x * 4;

    int beg = g_off[g * (NN + 1) + dst];
    int end = g_off[g * (NN + 1) + dst + 1];
    const int* srcs = g_csr_src + g * EE;
    const int* dout = &DEG_OUT(g, 0);

    float4 acc0 = make_float4(0.f, 0.f, 0.f, 0.f);
    float4 acc1 = make_float4(0.f, 0.f, 0.f, 0.f);
    int e = beg;
    for (; e + 1 < end; e += 2) {
        int s0 = srcs[e], s1 = srcs[e + 1];
        int d0 = dout[s0], d1 = dout[s1];
        float so0 = rsqrtf((float)(d0 > 1 ? d0 : 1));
        float so1 = rsqrtf((float)(d1 > 1 ? d1 : 1));
        const __half2* x0 = (const __half2*)(g_X16 + (size_t)s0 * IND + c);
        const __half2* x1 = (const __half2*)(g_X16 + (size_t)s1 * IND + c);
        __half2 a01 = x0[0], a23 = x0[1];
        __half2 b01 = x1[0], b23 = x1[1];
        float2 fa01 = __half22float2(a01), fa23 = __half22float2(a23);
        float2 fb01 = __half22float2(b01), fb23 = __half22float2(b23);
        acc0.x += fa01.x * so0; acc0.y += fa01.y * so0;
        acc0.z += fa23.x * so0; acc0.w += fa23.y * so0;
        acc1.x += fb01.x * so1; acc1.y += fb01.y * so1;
        acc1.z += fb23.x * so1; acc1.w += fb23.y * so1;
    }
    if (e < end) {
        int s0 = srcs[e];
        int d0 = dout[s0];
        float so0 = rsqrtf((float)(d0 > 1 ? d0 : 1));
        const __half2* x0 = (const __half2*)(g_X16 + (size_t)s0 * IND + c);
        __half2 a01 = x0[0], a23 = x0[1];
        float2 fa01 = __half22float2(a01), fa23 = __half22float2(a23);
        acc0.x += fa01.x * so0; acc0.y += fa01.y * so0;
        acc0.z += fa23.x * so0; acc0.w += fa23.y * so0;
    }
    acc0.x += acc1.x; acc0.y += acc1.y; acc0.z += acc1.z; acc0.w += acc1.w;

    int di = DEG_IN(g, dst);
    float rsv = rsqrtf((float)(di > 1 ? di : 1));

    size_t base = ((size_t)g * NN + dst) * IND + c;
    *(__half2*)(g_AX + base)     = __halves2half2(__float2half(acc0.x * rsv),
                                                  __float2half(acc0.y * rsv));
    *(__half2*)(g_AX + base + 2) = __halves2half2(__float2half(acc0.z * rsv),
                                                  __float2half(acc0.w * rsv));
}

// ============================================================================
// Single-pass fp16 GEMM: 128 threads, 4 warps (2x2), warp tile (BM/2) x 64.
// CTA tile BM x 128, BK=64, 3-stage cp.async pipeline, 1 barrier/chunk,
// swizzled ldmatrix, 2 CTAs/SM.
// mode 1: g=blockIdx.z; A=g_AX[g] (K=512), B=g_Bt[g]; tanh -> g_H
// mode 2: A=g_H (K=1536), B=g_BtL; +bias0 -> outp
// ============================================================================
#define NSTAGE 3

template<int BM>
__device__ __forceinline__ void prefetch_chunk(uint32_t sdst,
        const __half* __restrict__ A, const __half* __restrict__ B,
        int kc, int m0, int n0, int K, int tid) {
    const int TOT = (BM + 128) * 8;   // 16B segments
    #pragma unroll
    for (int i = tid; i < TOT; i += 128) {
        int row = i >> 3;
        int col = (i & 7) * 16;
        if (row < BM) {
            int mrow = m0 + row; if (mrow >= NN) mrow = NN - 1;  // clamped rows never stored
            uint32_t swz = ((uint32_t)(row * 128 + col)) ^ ((uint32_t)(row & 7) << 4);
            CP16(sdst + swz, (const char*)(A + (size_t)mrow * K) + kc * 128 + col);
        } else {
            int r2 = row - BM;
            uint32_t swz = ((uint32_t)(r2 * 128 + col)) ^ ((uint32_t)(r2 & 7) << 4);
            CP16(sdst + BM * 128 + swz, (const char*)(B + (size_t)(n0 + r2) * K) + kc * 128 + col);
        }
    }
}

template<int BM, int MI>
__global__ void __launch_bounds__(128, 2)
mma_gemm_kernel(float* outp, const float* __restrict__ bias0,
                const float* __restrict__ bias1, const float* __restrict__ bias2,
                int mode, int K) {
    constexpr int SBYTES = (BM + 128) * 128;
    extern __shared__ char smem_raw[];
    uint32_t sb0 = smem_to_u32(smem_raw);
    uint32_t sb = (sb0 + 1023) & ~1023u;

    int g = blockIdx.z;
    const __half *A, *B;
    const float* bias;
    if (mode == 1) {
        A = g_AX + (size_t)g * NN * IND;
        B = g_Bt + (size_t)g * HIDD * IND;
        bias = (g == 0) ? bias0 : (g == 1) ? bias1 : bias2;
    } else {
        A = g_H; B = g_BtL; bias = bias0;
    }

    int tid = threadIdx.x;
    int lane = tid & 31, wid = tid >> 5;
    int warpM = wid >> 1, warpN = wid & 1;     // 2x2 warp grid
    int n0 = blockIdx.x * 128;
    int m0 = blockIdx.y * BM;

    float acc[MI][8][4];
    #pragma unroll
    for (int i = 0; i < MI; i++)
        #pragma unroll
        for (int j = 0; j < 8; j++)
            #pragma unroll
            for (int r = 0; r < 4; r++) acc[i][j][r] = 0.f;

    int aRow = warpM * (BM / 2) + (lane & 15);
    int aCol = (lane >> 4) * 16;
    int bRow = warpN * 64 + (lane & 7) + (lane >> 4) * 8;
    int bCol = ((lane >> 3) & 1) * 16;

    int nk = K >> 6;
    prefetch_chunk<BM>(sb, A, B, 0, m0, n0, K, tid);
    CP_COMMIT();
    if (nk > 1) { prefetch_chunk<BM>(sb + SBYTES, A, B, 1, m0, n0, K, tid); }
    CP_COMMIT();

    for (int kc = 0; kc < nk; kc++) {
        if (kc + 2 < nk) CP_WAIT(1);
        else             CP_WAIT(0);
        __syncthreads();
        if (kc + 2 < nk) {
            prefetch_chunk<BM>(sb + ((kc + 2) % NSTAGE) * SBYTES, A, B, kc + 2, m0, n0, K, tid);
            CP_COMMIT();
        }

        uint32_t abase = sb + (kc % NSTAGE) * SBYTES;
        uint32_t bbase = abase + BM * 128;

        #pragma unroll
        for (int q = 0; q < 4; q++) {
            uint32_t bh[4][4];
            #pragma unroll
            for (int gi = 0; gi < 4; gi++) {
                int r = bRow + gi * 16;
                uint32_t off = ((uint32_t)(r * 128 + q * 32 + bCol)) ^ ((uint32_t)(r & 7) << 4);
                LDSM_X4(bh[gi][0], bh[gi][1], bh[gi][2], bh[gi][3], bbase + off);
            }
            #pragma unroll
            for (int mi = 0; mi < MI; mi++) {
                int r = aRow + mi * 16;
                uint32_t off = ((uint32_t)(r * 128 + q * 32 + aCol)) ^ ((uint32_t)(r & 7) << 4);
                uint32_t ah[4];
                LDSM_X4(ah[0], ah[1], ah[2], ah[3], abase + off);
                #pragma unroll
                for (int nj = 0; nj < 8; nj++) {
                    uint32_t bf[2] = { bh[nj >> 1][(nj & 1) * 2], bh[nj >> 1][(nj & 1) * 2 + 1] };
                    MMA_F16(acc[mi][nj], ah, bf);
                }
            }
        }
    }

    float alpha = (mode == 1) ? g_alpha[g] : 0.f;

    #pragma unroll
    for (int mi = 0; mi < MI; mi++) {
        #pragma unroll
        for (int nj = 0; nj < 8; nj++) {
            int m = m0 + warpM * (BM / 2) + mi * 16 + (lane >> 2);
            int n = n0 + warpN * 64 + nj * 8 + (lane & 3) * 2;
            float c0 = acc[mi][nj][0], c1 = acc[mi][nj][1];
            float c2 = acc[mi][nj][2], c3 = acc[mi][nj][3];
            float bx = bias[n], by = bias[n + 1];
            if (mode == 1) {
                size_t coln = (size_t)g * HIDD + n;
                if (m < NN) {
                    float h0 = fast_tanh(alpha * (c0 + bx));
                    float h1 = fast_tanh(alpha * (c1 + by));
                    *(__half2*)(g_H + (size_t)m * CONCAT + coln) =
                        __halves2half2(__float2half(h0), __float2half(h1));
                }
                if (m + 8 < NN) {
                    float h2 = fast_tanh(alpha * (c2 + bx));
                    float h3 = fast_tanh(alpha * (c3 + by));
                    *(__half2*)(g_H + (size_t)(m + 8) * CONCAT + coln) =
                        __halves2half2(__float2half(h2), __float2half(h3));
                }
            } else {
                if (m < NN)
                    *(float2*)(outp + (size_t)m * OUTD + n) = make_float2(c0 + bx, c1 + by);
                if (m + 8 < NN)
                    *(float2*)(outp + (size_t)(m + 8) * OUTD + n) = make_float2(c2 + bx, c3 + by);
            }
        }
    }
}

#define SMEM1 (1024 + NSTAGE * (128 + 128) * 128)   // 99328
#define SMEM2 (1024 + NSTAGE * (64 + 128) * 128)    // 74752

// ============================================================================
// Launch — R11 structure: fused launches; conv_x/conv_w forked on s2.
// ============================================================================
extern "C" void kernel_launch(void* const* d_in, const int* in_sizes, int n_in,
                              void* d_out, int out_size) {
    const float* x = nullptr;
    const int*   e[GG]  = {nullptr, nullptr, nullptr};
    const float* W[GG]  = {nullptr, nullptr, nullptr};
    const float* b[GG]  = {nullptr, nullptr, nullptr};
    const float* alphas = nullptr;
    const float* W_lin  = nullptr;
    const float* b_lin  = nullptr;
    int ne = 0, nw = 0, nb = 0;

    for (int i = 0; i < n_in; i++) {
        int sz = in_sizes[i];
        if      (sz == NN * IND)      x = (const float*)d_in[i];
        else if (sz == 2 * EE)        { if (ne < GG) e[ne++] = (const int*)d_in[i]; }
        else if (sz == IND * HIDD)    { if (nw < GG) W[nw++] = (const float*)d_in[i]; }
        else if (sz == HIDD)          { if (nb < GG) b[nb++] = (const float*)d_in[i]; }
        else if (sz == GG)            alphas = (const float*)d_in[i];
        else if (sz == CONCAT * OUTD) W_lin = (const float*)d_in[i];
        else if (sz == OUTD)          b_lin = (const float*)d_in[i];
    }
    float* out = (float*)d_out;

    static cudaStream_t s2 = nullptr;
    static cudaEvent_t ev_fork = nullptr, ev_convx = nullptr, ev_convw = nullptr;
    if (!s2) {
        cudaStreamCreateWithFlags(&s2, cudaStreamNonBlocking);
        cudaEventCreateWithFlags(&ev_fork, cudaEventDisableTiming);
        cudaEventCreateWithFlags(&ev_convx, cudaEventDisableTiming);
        cudaEventCreateWithFlags(&ev_convw, cudaEventDisableTiming);
    }

    cudaFuncSetAttribute((const void*)mma_gemm_kernel<128, 4>,
                         cudaFuncAttributeMaxDynamicSharedMemorySize, SMEM1);
    cudaFuncSetAttribute((const void*)mma_gemm_kernel<64, 2>,
                         cudaFuncAttributeMaxDynamicSharedMemorySize, SMEM2);

    void* degp = nullptr;
    cudaGetSymbolAddress(&degp, g_deg);
    cudaMemsetAsync(degp, 0, sizeof(int) * 2 * GG * NN, 0);

    // Fork conversions onto s2 (overlap with CSR build on s0)
    cudaEventRecord(ev_fork, 0);
    cudaStreamWaitEvent(s2, ev_fork, 0);
    conv_x_kernel<<<1184, 256, 0, s2>>>(x);
    cudaEventRecord(ev_convx, s2);
    conv_w_kernel<<<256, 256, 0, s2>>>(W[0], W[1], W[2], W_lin);
    cudaEventRecord(ev_convw, s2);

    hist_kernel<<<(GG * EE + 255) / 256, 256>>>(e[0], e[1], e[2]);
    scan_kernel<<<GG, 1024>>>(alphas);
    fill_kernel<<<(GG * EE + 255) / 256, 256>>>(e[0], e[1], e[2]);

    // agg needs CSR (s0, ordered) + X16
    cudaStreamWaitEvent(0, ev_convx, 0);
    dim3 gridA(NN, GG);
    agg_x_kernel<<<gridA, 128>>>();

    // GEMM1 additionally needs Bt (conv_w)
    cudaStreamWaitEvent(0, ev_convw, 0);
    int mtiles1 = (NN + 127) / 128;          // 235
    dim3 grid1(HIDD / 128, mtiles1, GG);     // 4 x 235 x 3
    mma_gemm_kernel<128, 4><<<grid1, 128, SMEM1>>>(nullptr, b[0], b[1], b[2], 1, IND);

    // GEMM2
    int mtiles2 = (NN + 63) / 64;            // 469
    dim3 grid2(OUTD / 128, mtiles2, 1);      // 2 x 469
    mma_gemm_kernel<64, 2><<<grid2, 128, SMEM2>>>(out, b_lin, nullptr, nullptr, 2, CONCAT);
}

// round 14
// speedup vs baseline: 1.2239x; 1.1218x over previous
#include <cuda_runtime.h>
#include <cuda_fp16.h>
#include <math.h>
#include <stdint.h>

// Problem constants
#define NN 30000      // nodes
#define EE 150000     // edges per graph
#define IND 512
#define HIDD 512
#define OUTD 256
#define GG 3
#define CONCAT (HIDD * GG)   // 1536
#define NTILES 30            // ceil(NN/1024)

// ============================================================================
// Scratch (device globals)
// ============================================================================
__device__ __half g_X16[(size_t)NN * IND];        // x in fp16
__device__ __half g_AX[(size_t)GG * NN * IND];    // aggregated, scaled X (fp16)
__device__ __half g_H [(size_t)NN * CONCAT];      // tanh(...) (fp16)
__device__ __half g_Bt [(size_t)CONCAT * IND];    // [W0|W1|W2]^T : row n, col k (fp16)
__device__ __half g_BtL[(size_t)OUTD * CONCAT];   // W_lin^T : row n, col k (fp16)
__device__ int   g_deg[2 * GG * NN];              // [0,GG*NN)=deg_in, rest deg_out
__device__ int   g_off    [GG * (NN + 1)];
__device__ int   g_cursor [GG * NN];
__device__ int   g_csr_src[GG * EE];
__device__ int   g_spine  [GG * 32];
__device__ float g_alpha  [GG];

#define DEG_IN(g, i)  g_deg[(g) * NN + (i)]
#define DEG_OUT(g, i) g_deg[GG * NN + (g) * NN + (i)]

// ============================================================================
// PTX helpers (plain-sm_103-legal: cp.async / ldmatrix / mma.sync)
// ============================================================================
__device__ __forceinline__ uint32_t smem_to_u32(const void* p) {
    uint32_t a;
    asm("{ .reg .u64 t; cvta.to.shared.u64 t, %1; cvt.u32.u64 %0, t; }" : "=r"(a) : "l"(p));
    return a;
}
#define CP16(dst32, src) \
    asm volatile("cp.async.cg.shared.global [%0], [%1], 16;" :: "r"(dst32), "l"(src))
#define CP_COMMIT() asm volatile("cp.async.commit_group;" ::: "memory")
#define CP_WAIT(n)  asm volatile("cp.async.wait_group %0;" :: "n"(n) : "memory")

#define LDSM_X4(r0, r1, r2, r3, addr) \
    asm volatile("ldmatrix.sync.aligned.m8n8.x4.shared.b16 {%0,%1,%2,%3}, [%4];" \
        : "=r"(r0), "=r"(r1), "=r"(r2), "=r"(r3) : "r"(addr))

#define MMA_F16(c, a, b) \
    asm volatile("mma.sync.aligned.m16n8k16.row.col.f32.f16.f16.f32 " \
        "{%0,%1,%2,%3}, {%4,%5,%6,%7}, {%8,%9}, {%0,%1,%2,%3};" \
        : "+f"((c)[0]), "+f"((c)[1]), "+f"((c)[2]), "+f"((c)[3]) \
        : "r"((a)[0]), "r"((a)[1]), "r"((a)[2]), "r"((a)[3]), "r"((b)[0]), "r"((b)[1]))

// fast tanh: 1 - 2/(exp(2x)+1); rel err ~1e-6
__device__ __forceinline__ float fast_tanh(float x) {
    float e = __expf(2.0f * x);
    return 1.0f - __fdividef(2.0f, e + 1.0f);
}

// ============================================================================
// Setup kernels
// ============================================================================
__global__ void hist_kernel(const int* __restrict__ e0, const int* __restrict__ e1,
                            const int* __restrict__ e2) {
    int i = blockIdx.x * blockDim.x + threadIdx.x;
    if (i >= GG * EE) return;
    int g = i / EE, idx = i - g * EE;
    const int* e = (g == 0) ? e0 : (g == 1) ? e1 : e2;
    atomicAdd(&DEG_OUT(g, e[idx]), 1);
    atomicAdd(&DEG_IN (g, e[EE + idx]), 1);
}

// Phase A: per-tile block scan (coalesced), partial exclusive offsets + spine.
__global__ void __launch_bounds__(1024)
scanA_kernel() {
    int t = blockIdx.x, g = blockIdx.y;
    int tid = threadIdx.x;
    int i = t * 1024 + tid;
    const int* cnt = &DEG_IN(g, 0);
    int v = (i < NN) ? cnt[i] : 0;

    int lane = tid & 31, wid = tid >> 5;
    int incl = v;
    #pragma unroll
    for (int d = 1; d < 32; d <<= 1) {
        int n = __shfl_up_sync(0xFFFFFFFFu, incl, d);
        if (lane >= d) incl += n;
    }
    __shared__ int wsum[32];
    if (lane == 31) wsum[wid] = incl;
    __syncthreads();
    if (wid == 0) {
        int s = wsum[lane];
        #pragma unroll
        for (int d = 1; d < 32; d <<= 1) {
            int n = __shfl_up_sync(0xFFFFFFFFu, s, d);
            if (lane >= d) s += n;
        }
        wsum[lane] = s;
    }
    __syncthreads();
    int excl = incl - v + (wid > 0 ? wsum[wid - 1] : 0);
    if (i < NN) g_off[g * (NN + 1) + i] = excl;          // pre-spine partial
    if (tid == 1023) g_spine[g * 32 + t] = excl + v;     // tile total
}

// Phase C: add spine prefix, write final off + cursor; softmax(alphas) in (0,0).
__global__ void __launch_bounds__(1024)
scanC_kernel(const float* __restrict__ alphas) {
    int t = blockIdx.x, g = blockIdx.y;
    __shared__ int pre[2];
    if (threadIdx.x == 0) {
        int p = 0, tot = 0;
        #pragma unroll
        for (int j = 0; j < NTILES; j++) {
            int s = g_spine[g * 32 + j];
            if (j < t) p += s;
            tot += s;
        }
        pre[0] = p; pre[1] = tot;
        if (g == 0 && t == 0) {
            float m = alphas[0];
            for (int k = 1; k < GG; k++) m = fmaxf(m, alphas[k]);
            float s = 0.f, e[GG];
            for (int k = 0; k < GG; k++) { e[k] = expf(alphas[k] - m); s += e[k]; }
            for (int k = 0; k < GG; k++) g_alpha[k] = e[k] / s;
        }
    }
    __syncthreads();
    int p = pre[0];
    int i = t * 1024 + threadIdx.x;
    if (i < NN) {
        int o = g_off[g * (NN + 1) + i] + p;
        g_off[g * (NN + 1) + i] = o;
        g_cursor[g * NN + i] = o;
    }
    if (t == 0 && threadIdx.x == 0) g_off[g * (NN + 1) + NN] = pre[1];
}

__global__ void fill_kernel(const int* __restrict__ e0, const int* __restrict__ e1,
                            const int* __restrict__ e2) {
    int i = blockIdx.x * blockDim.x + threadIdx.x;
    if (i >= GG * EE) return;
    int g = i / EE, idx = i - g * EE;
    const int* e = (g == 0) ? e0 : (g == 1) ? e1 : e2;
    int src = e[idx];
    int dst = e[EE + idx];
    int p = atomicAdd(&g_cursor[g * NN + dst], 1);
    g_csr_src[g * EE + p] = src;
}

// ============================================================================
// Merged conversion (vectorized): x->fp16 ; W, W_lin -> transposed fp16
// ============================================================================
#define CX4_TOTAL  (NN * IND / 4)
#define CW_TOTAL   (GG * IND * HIDD)
#define CWL_TOTAL  (CONCAT * OUTD)
#define CONV_TOTAL (CX4_TOTAL + CW_TOTAL + CWL_TOTAL)

__global__ void conv_all_kernel(const float* __restrict__ x,
                                const float* __restrict__ W0,
                                const float* __restrict__ W1,
                                const float* __restrict__ W2,
                                const float* __restrict__ WL) {
    int i = blockIdx.x * blockDim.x + threadIdx.x;
    const float4* x4 = (const float4*)x;
    __half2* X2 = (__half2*)g_X16;
    for (int idx = i; idx < CONV_TOTAL; idx += gridDim.x * blockDim.x) {
        if (idx < CX4_TOTAL) {
            float4 v = x4[idx];
            X2[idx * 2]     = __floats2half2_rn(v.x, v.y);
            X2[idx * 2 + 1] = __floats2half2_rn(v.z, v.w);
        } else if (idx < CX4_TOTAL + CW_TOTAL) {
            int t = idx - CX4_TOTAL;
            int k = t & 511;
            int n = (t >> 9) & 511;
            int g = t >> 18;
            const float* W = (g == 0) ? W0 : (g == 1) ? W1 : W2;
            g_Bt[(size_t)(g * HIDD + n) * IND + k] = __float2half(W[k * HIDD + n]);
        } else {
            int t = idx - CX4_TOTAL - CW_TOTAL;
            int k = t % CONCAT;
            int n = t / CONCAT;
            g_BtL[(size_t)n * CONCAT + k] = __float2half(WL[k * OUTD + n]);
        }
    }
}

// ============================================================================
// Pre-GEMM aggregation on fp16 X (fp32 accum, fp16 out), grid (NN, GG),
// edge loop unrolled x2 with dual accumulators.
// ============================================================================
__global__ void __launch_bounds__(128)
agg_x_kernel() {
    int dst = blockIdx.x;
    int g = blockIdx.y;
    int c = threadIdx.x * 4;

    int beg = g_off[g * (NN + 1) + dst];
    int end = g_off[g * (NN + 1) + dst + 1];
    const int* srcs = g_csr_src + g * EE;
    const int* dout = &DEG_OUT(g, 0);

    float4 acc0 = make_float4(0.f, 0.f, 0.f, 0.f);
    float4 acc1 = make_float4(0.f, 0.f, 0.f, 0.f);
    int e = beg;
    for (; e + 1 < end; e += 2) {
        int s0 = srcs[e], s1 = srcs[e + 1];
        int d0 = dout[s0], d1 = dout[s1];
        float so0 = rsqrtf((float)(d0 > 1 ? d0 : 1));
        float so1 = rsqrtf((float)(d1 > 1 ? d1 : 1));
        const __half2* x0 = (const __half2*)(g_X16 + (size_t)s0 * IND + c);
        const __half2* x1 = (const __half2*)(g_X16 + (size_t)s1 * IND + c);
        __half2 a01 = x0[0], a23 = x0[1];
        __half2 b01 = x1[0], b23 = x1[1];
        float2 fa01 = __half22float2(a01), fa23 = __half22float2(a23);
        float2 fb01 = __half22float2(b01), fb23 = __half22float2(b23);
        acc0.x += fa01.x * so0; acc0.y += fa01.y * so0;
        acc0.z += fa23.x * so0; acc0.w += fa23.y * so0;
        acc1.x += fb01.x * so1; acc1.y += fb01.y * so1;
        acc1.z += fb23.x * so1; acc1.w += fb23.y * so1;
    }
    if (e < end) {
        int s0 = srcs[e];
        int d0 = dout[s0];
        float so0 = rsqrtf((float)(d0 > 1 ? d0 : 1));
        const __half2* x0 = (const __half2*)(g_X16 + (size_t)s0 * IND + c);
        __half2 a01 = x0[0], a23 = x0[1];
        float2 fa01 = __half22float2(a01), fa23 = __half22float2(a23);
        acc0.x += fa01.x * so0; acc0.y += fa01.y * so0;
        acc0.z += fa23.x * so0; acc0.w += fa23.y * so0;
    }
    acc0.x += acc1.x; acc0.y += acc1.y; acc0.z += acc1.z; acc0.w += acc1.w;

    int di = DEG_IN(g, dst);
    float rsv = rsqrtf((float)(di > 1 ? di : 1));

    size_t base = ((size_t)g * NN + dst) * IND + c;
    *(__half2*)(g_AX + base)     = __halves2half2(__float2half(acc0.x * rsv),
                                                  __float2half(acc0.y * rsv));
    *(__half2*)(g_AX + base + 2) = __halves2half2(__float2half(acc0.z * rsv),
                                                  __float2half(acc0.w * rsv));
}

// ============================================================================
// Single-pass fp16 GEMM: 128 threads, 4 warps (2x2), warp tile (BM/2) x 64.
// CTA tile BM x 128, BK=64, 3-stage cp.async pipeline, 1 barrier/chunk,
// swizzled ldmatrix, 2 CTAs/SM.
// mode 1: g=blockIdx.z; A=g_AX[g] (K=512), B=g_Bt[g]; tanh -> g_H
// mode 2: A=g_H (K=1536), B=g_BtL; +bias0 -> outp
// ============================================================================
#define NSTAGE 3

template<int BM>
__device__ __forceinline__ void prefetch_chunk(uint32_t sdst,
        const __half* __restrict__ A, const __half* __restrict__ B,
        int kc, int m0, int n0, int K, int tid) {
    const int TOT = (BM + 128) * 8;   // 16B segments
    #pragma unroll
    for (int i = tid; i < TOT; i += 128) {
        int row = i >> 3;
        int col = (i & 7) * 16;
        if (row < BM) {
            int mrow = m0 + row; if (mrow >= NN) mrow = NN - 1;  // clamped rows never stored
            uint32_t swz = ((uint32_t)(row * 128 + col)) ^ ((uint32_t)(row & 7) << 4);
            CP16(sdst + swz, (const char*)(A + (size_t)mrow * K) + kc * 128 + col);
        } else {
            int r2 = row - BM;
            uint32_t swz = ((uint32_t)(r2 * 128 + col)) ^ ((uint32_t)(r2 & 7) << 4);
            CP16(sdst + BM * 128 + swz, (const char*)(B + (size_t)(n0 + r2) * K) + kc * 128 + col);
        }
    }
}

template<int BM, int MI>
__global__ void __launch_bounds__(128, 2)
mma_gemm_kernel(float* outp, const float* __restrict__ bias0,
                const float* __restrict__ bias1, const float* __restrict__ bias2,
                int mode, int K) {
    constexpr int SBYTES = (BM + 128) * 128;
    extern __shared__ char smem_raw[];
    uint32_t sb0 = smem_to_u32(smem_raw);
    uint32_t sb = (sb0 + 1023) & ~1023u;

    int g = blockIdx.z;
    const __half *A, *B;
    const float* bias;
    if (mode == 1) {
        A = g_AX + (size_t)g * NN * IND;
        B = g_Bt + (size_t)g * HIDD * IND;
        bias = (g == 0) ? bias0 : (g == 1) ? bias1 : bias2;
    } else {
        A = g_H; B = g_BtL; bias = bias0;
    }

    int tid = threadIdx.x;
    int lane = tid & 31, wid = tid >> 5;
    int warpM = wid >> 1, warpN = wid & 1;     // 2x2 warp grid
    int n0 = blockIdx.x * 128;
    int m0 = blockIdx.y * BM;

    float acc[MI][8][4];
    #pragma unroll
    for (int i = 0; i < MI; i++)
        #pragma unroll
        for (int j = 0; j < 8; j++)
            #pragma unroll
            for (int r = 0; r < 4; r++) acc[i][j][r] = 0.f;

    int aRow = warpM * (BM / 2) + (lane & 15);
    int aCol = (lane >> 4) * 16;
    int bRow = warpN * 64 + (lane & 7) + (lane >> 4) * 8;
    int bCol = ((lane >> 3) & 1) * 16;

    int nk = K >> 6;
    prefetch_chunk<BM>(sb, A, B, 0, m0, n0, K, tid);
    CP_COMMIT();
    if (nk > 1) { prefetch_chunk<BM>(sb + SBYTES, A, B, 1, m0, n0, K, tid); }
    CP_COMMIT();

    for (int kc = 0; kc < nk; kc++) {
        if (kc + 2 < nk) CP_WAIT(1);
        else             CP_WAIT(0);
        __syncthreads();
        if (kc + 2 < nk) {
            prefetch_chunk<BM>(sb + ((kc + 2) % NSTAGE) * SBYTES, A, B, kc + 2, m0, n0, K, tid);
            CP_COMMIT();
        }

        uint32_t abase = sb + (kc % NSTAGE) * SBYTES;
        uint32_t bbase = abase + BM * 128;

        #pragma unroll
        for (int q = 0; q < 4; q++) {
            uint32_t bh[4][4];
            #pragma unroll
            for (int gi = 0; gi < 4; gi++) {
                int r = bRow + gi * 16;
                uint32_t off = ((uint32_t)(r * 128 + q * 32 + bCol)) ^ ((uint32_t)(r & 7) << 4);
                LDSM_X4(bh[gi][0], bh[gi][1], bh[gi][2], bh[gi][3], bbase + off);
            }
            #pragma unroll
            for (int mi = 0; mi < MI; mi++) {
                int r = aRow + mi * 16;
                uint32_t off = ((uint32_t)(r * 128 + q * 32 + aCol)) ^ ((uint32_t)(r & 7) << 4);
                uint32_t ah[4];
                LDSM_X4(ah[0], ah[1], ah[2], ah[3], abase + off);
                #pragma unroll
                for (int nj = 0; nj < 8; nj++) {
                    uint32_t bf[2] = { bh[nj >> 1][(nj & 1) * 2], bh[nj >> 1][(nj & 1) * 2 + 1] };
                    MMA_F16(acc[mi][nj], ah, bf);
                }
            }
        }
    }

    float alpha = (mode == 1) ? g_alpha[g] : 0.f;

    #pragma unroll
    for (int mi = 0; mi < MI; mi++) {
        #pragma unroll
        for (int nj = 0; nj < 8; nj++) {
            int m = m0 + warpM * (BM / 2) + mi * 16 + (lane >> 2);
            int n = n0 + warpN * 64 + nj * 8 + (lane & 3) * 2;
            float c0 = acc[mi][nj][0], c1 = acc[mi][nj][1];
            float c2 = acc[mi][nj][2], c3 = acc[mi][nj][3];
            float bx = bias[n], by = bias[n + 1];
            if (mode == 1) {
                size_t coln = (size_t)g * HIDD + n;
                if (m < NN) {
                    float h0 = fast_tanh(alpha * (c0 + bx));
                    float h1 = fast_tanh(alpha * (c1 + by));
                    *(__half2*)(g_H + (size_t)m * CONCAT + coln) =
                        __halves2half2(__float2half(h0), __float2half(h1));
                }
                if (m + 8 < NN) {
                    float h2 = fast_tanh(alpha * (c2 + bx));
                    float h3 = fast_tanh(alpha * (c3 + by));
                    *(__half2*)(g_H + (size_t)(m + 8) * CONCAT + coln) =
                        __halves2half2(__float2half(h2), __float2half(h3));
                }
            } else {
                if (m < NN)
                    *(float2*)(outp + (size_t)m * OUTD + n) = make_float2(c0 + bx, c1 + by);
                if (m + 8 < NN)
                    *(float2*)(outp + (size_t)(m + 8) * OUTD + n) = make_float2(c2 + bx, c3 + by);
            }
        }
    }
}

#define SMEM1 (1024 + NSTAGE * (128 + 128) * 128)   // 99328
#define SMEM2 (1024 + NSTAGE * (64 + 128) * 128)    // 74752

// ============================================================================
// Launch — R11 structure + fast two-phase scan.
// ============================================================================
extern "C" void kernel_launch(void* const* d_in, const int* in_sizes, int n_in,
                              void* d_out, int out_size) {
    const float* x = nullptr;
    const int*   e[GG]  = {nullptr, nullptr, nullptr};
    const float* W[GG]  = {nullptr, nullptr, nullptr};
    const float* b[GG]  = {nullptr, nullptr, nullptr};
    const float* alphas = nullptr;
    const float* W_lin  = nullptr;
    const float* b_lin  = nullptr;
    int ne = 0, nw = 0, nb = 0;

    for (int i = 0; i < n_in; i++) {
        int sz = in_sizes[i];
        if      (sz == NN * IND)      x = (const float*)d_in[i];
        else if (sz == 2 * EE)        { if (ne < GG) e[ne++] = (const int*)d_in[i]; }
        else if (sz == IND * HIDD)    { if (nw < GG) W[nw++] = (const float*)d_in[i]; }
        else if (sz == HIDD)          { if (nb < GG) b[nb++] = (const float*)d_in[i]; }
        else if (sz == GG)            alphas = (const float*)d_in[i];
        else if (sz == CONCAT * OUTD) W_lin = (const float*)d_in[i];
        else if (sz == OUTD)          b_lin = (const float*)d_in[i];
    }
    float* out = (float*)d_out;

    static cudaStream_t s2 = nullptr;
    static cudaEvent_t ev_fork = nullptr, ev_conv = nullptr;
    if (!s2) {
        cudaStreamCreateWithFlags(&s2, cudaStreamNonBlocking);
        cudaEventCreateWithFlags(&ev_fork, cudaEventDisableTiming);
        cudaEventCreateWithFlags(&ev_conv, cudaEventDisableTiming);
    }

    cudaFuncSetAttribute((const void*)mma_gemm_kernel<128, 4>,
                         cudaFuncAttributeMaxDynamicSharedMemorySize, SMEM1);
    cudaFuncSetAttribute((const void*)mma_gemm_kernel<64, 2>,
                         cudaFuncAttributeMaxDynamicSharedMemorySize, SMEM2);

    void* degp = nullptr;
    cudaGetSymbolAddress(&degp, g_deg);
    cudaMemsetAsync(degp, 0, sizeof(int) * 2 * GG * NN, 0);

    // Fork conversions onto s2 (overlap with CSR build on s0)
    cudaEventRecord(ev_fork, 0);
    cudaStreamWaitEvent(s2, ev_fork, 0);
    conv_all_kernel<<<1184, 256, 0, s2>>>(x, W[0], W[1], W[2], W_lin);
    cudaEventRecord(ev_conv, s2);

    hist_kernel<<<(GG * EE + 255) / 256, 256>>>(e[0], e[1], e[2]);
    dim3 gridS(NTILES, GG);
    scanA_kernel<<<gridS, 1024>>>();
    scanC_kernel<<<gridS, 1024>>>(alphas);
    fill_kernel<<<(GG * EE + 255) / 256, 256>>>(e[0], e[1], e[2]);

    // Join: agg needs CSR (s0, ordered) + X16 (s2)
    cudaStreamWaitEvent(0, ev_conv, 0);

    dim3 gridA(NN, GG);
    agg_x_kernel<<<gridA, 128>>>();

    // GEMM1: fused, all 3 branches, BM=128
    int mtiles1 = (NN + 127) / 128;          // 235
    dim3 grid1(HIDD / 128, mtiles1, GG);     // 4 x 235 x 3
    mma_gemm_kernel<128, 4><<<grid1, 128, SMEM1>>>(nullptr, b[0], b[1], b[2], 1, IND);

    // GEMM2: BM=64 (938 CTAs)
    int mtiles2 = (NN + 63) / 64;            // 469
    dim3 grid2(OUTD / 128, mtiles2, 1);      // 2 x 469
    mma_gemm_kernel<64, 2><<<grid2, 128, SMEM2>>>(out, b_lin, nullptr, nullptr, 2, CONCAT);
}

// round 15
// speedup vs baseline: 1.3550x; 1.1072x over previous
#include <cuda_runtime.h>
#include <cuda_fp16.h>
#include <math.h>
#include <stdint.h>

// Problem constants
#define NN 30000      // nodes
#define EE 150000     // edges per graph
#define IND 512
#define HIDD 512
#define OUTD 256
#define GG 3
#define CONCAT (HIDD * GG)   // 1536
#define NTILES 30            // ceil(NN/1024)

// ============================================================================
// Scratch (device globals)
// ============================================================================
__device__ __half g_X16[(size_t)NN * IND];        // x in fp16
__device__ __half g_AX[(size_t)GG * NN * IND];    // aggregated, scaled X (fp16)
__device__ __half g_H [(size_t)NN * CONCAT];      // tanh(...) (fp16)
__device__ __half g_Bt [(size_t)CONCAT * IND];    // [W0|W1|W2]^T : row n, col k (fp16)
__device__ __half g_BtL[(size_t)OUTD * CONCAT];   // W_lin^T : row n, col k (fp16)
__device__ int   g_deg[2 * GG * NN];              // [0,GG*NN)=deg_in, rest deg_out
__device__ int   g_off    [GG * (NN + 1)];
__device__ int   g_cursor [GG * NN];
__device__ int   g_csr_src[GG * EE];
__device__ int   g_spine  [GG * 32];
__device__ float g_alpha  [GG];

#define DEG_IN(g, i)  g_deg[(g) * NN + (i)]
#define DEG_OUT(g, i) g_deg[GG * NN + (g) * NN + (i)]

// ============================================================================
// PTX helpers (plain-sm_103-legal: cp.async / ldmatrix / mma.sync)
// ============================================================================
__device__ __forceinline__ uint32_t smem_to_u32(const void* p) {
    uint32_t a;
    asm("{ .reg .u64 t; cvta.to.shared.u64 t, %1; cvt.u32.u64 %0, t; }" : "=r"(a) : "l"(p));
    return a;
}
#define CP16(dst32, src) \
    asm volatile("cp.async.cg.shared.global [%0], [%1], 16;" :: "r"(dst32), "l"(src))
#define CP_COMMIT() asm volatile("cp.async.commit_group;" ::: "memory")
#define CP_WAIT(n)  asm volatile("cp.async.wait_group %0;" :: "n"(n) : "memory")

#define LDSM_X4(r0, r1, r2, r3, addr) \
    asm volatile("ldmatrix.sync.aligned.m8n8.x4.shared.b16 {%0,%1,%2,%3}, [%4];" \
        : "=r"(r0), "=r"(r1), "=r"(r2), "=r"(r3) : "r"(addr))

#define MMA_F16(c, a, b) \
    asm volatile("mma.sync.aligned.m16n8k16.row.col.f32.f16.f16.f32 " \
        "{%0,%1,%2,%3}, {%4,%5,%6,%7}, {%8,%9}, {%0,%1,%2,%3};" \
        : "+f"((c)[0]), "+f"((c)[1]), "+f"((c)[2]), "+f"((c)[3]) \
        : "r"((a)[0]), "r"((a)[1]), "r"((a)[2]), "r"((a)[3]), "r"((b)[0]), "r"((b)[1]))

// fast tanh: 1 - 2/(exp(2x)+1); rel err ~1e-6
__device__ __forceinline__ float fast_tanh(float x) {
    float e = __expf(2.0f * x);
    return 1.0f - __fdividef(2.0f, e + 1.0f);
}

// ============================================================================
// Setup kernels
// ============================================================================
__global__ void hist_kernel(const int* __restrict__ e0, const int* __restrict__ e1,
                            const int* __restrict__ e2) {
    int i = blockIdx.x * blockDim.x + threadIdx.x;
    if (i >= GG * EE) return;
    int g = i / EE, idx = i - g * EE;
    const int* e = (g == 0) ? e0 : (g == 1) ? e1 : e2;
    atomicAdd(&DEG_OUT(g, e[idx]), 1);
    atomicAdd(&DEG_IN (g, e[EE + idx]), 1);
}

// Phase A: per-tile block scan (coalesced), partial exclusive offsets + spine.
__global__ void __launch_bounds__(1024)
scanA_kernel() {
    int t = blockIdx.x, g = blockIdx.y;
    int tid = threadIdx.x;
    int i = t * 1024 + tid;
    const int* cnt = &DEG_IN(g, 0);
    int v = (i < NN) ? cnt[i] : 0;

    int lane = tid & 31, wid = tid >> 5;
    int incl = v;
    #pragma unroll
    for (int d = 1; d < 32; d <<= 1) {
        int n = __shfl_up_sync(0xFFFFFFFFu, incl, d);
        if (lane >= d) incl += n;
    }
    __shared__ int wsum[32];
    if (lane == 31) wsum[wid] = incl;
    __syncthreads();
    if (wid == 0) {
        int s = wsum[lane];
        #pragma unroll
        for (int d = 1; d < 32; d <<= 1) {
            int n = __shfl_up_sync(0xFFFFFFFFu, s, d);
            if (lane >= d) s += n;
        }
        wsum[lane] = s;
    }
    __syncthreads();
    int excl = incl - v + (wid > 0 ? wsum[wid - 1] : 0);
    if (i < NN) g_off[g * (NN + 1) + i] = excl;          // pre-spine partial
    if (tid == 1023) g_spine[g * 32 + t] = excl + v;     // tile total
}

// Phase C: add spine prefix, write final off + cursor; softmax(alphas) in (0,0).
__global__ void __launch_bounds__(1024)
scanC_kernel(const float* __restrict__ alphas) {
    int t = blockIdx.x, g = blockIdx.y;
    __shared__ int pre[2];
    if (threadIdx.x == 0) {
        int p = 0, tot = 0;
        #pragma unroll
        for (int j = 0; j < NTILES; j++) {
            int s = g_spine[g * 32 + j];
            if (j < t) p += s;
            tot += s;
        }
        pre[0] = p; pre[1] = tot;
        if (g == 0 && t == 0) {
            float m = alphas[0];
            for (int k = 1; k < GG; k++) m = fmaxf(m, alphas[k]);
            float s = 0.f, e[GG];
            for (int k = 0; k < GG; k++) { e[k] = expf(alphas[k] - m); s += e[k]; }
            for (int k = 0; k < GG; k++) g_alpha[k] = e[k] / s;
        }
    }
    __syncthreads();
    int p = pre[0];
    int i = t * 1024 + threadIdx.x;
    if (i < NN) {
        int o = g_off[g * (NN + 1) + i] + p;
        g_off[g * (NN + 1) + i] = o;
        g_cursor[g * NN + i] = o;
    }
    if (t == 0 && threadIdx.x == 0) g_off[g * (NN + 1) + NN] = pre[1];
}

__global__ void fill_kernel(const int* __restrict__ e0, const int* __restrict__ e1,
                            const int* __restrict__ e2) {
    int i = blockIdx.x * blockDim.x + threadIdx.x;
    if (i >= GG * EE) return;
    int g = i / EE, idx = i - g * EE;
    const int* e = (g == 0) ? e0 : (g == 1) ? e1 : e2;
    int src = e[idx];
    int dst = e[EE + idx];
    int p = atomicAdd(&g_cursor[g * NN + dst], 1);
    g_csr_src[g * EE + p] = src;
}

// ============================================================================
// Merged conversion (vectorized): x->fp16 ; W, W_lin -> transposed fp16
// ============================================================================
#define CX4_TOTAL  (NN * IND / 4)
#define CW_TOTAL   (GG * IND * HIDD)
#define CWL_TOTAL  (CONCAT * OUTD)
#define CONV_TOTAL (CX4_TOTAL + CW_TOTAL + CWL_TOTAL)

__global__ void conv_all_kernel(const float* __restrict__ x,
                                const float* __restrict__ W0,
                                const float* __restrict__ W1,
                                const float* __restrict__ W2,
                                const float* __restrict__ WL) {
    int i = blockIdx.x * blockDim.x + threadIdx.x;
    const float4* x4 = (const float4*)x;
    __half2* X2 = (__half2*)g_X16;
    for (int idx = i; idx < CONV_TOTAL; idx += gridDim.x * blockDim.x) {
        if (idx < CX4_TOTAL) {
            float4 v = x4[idx];
            X2[idx * 2]     = __floats2half2_rn(v.x, v.y);
            X2[idx * 2 + 1] = __floats2half2_rn(v.z, v.w);
        } else if (idx < CX4_TOTAL + CW_TOTAL) {
            int t = idx - CX4_TOTAL;
            int k = t & 511;
            int n = (t >> 9) & 511;
            int g = t >> 18;
            const float* W = (g == 0) ? W0 : (g == 1) ? W1 : W2;
            g_Bt[(size_t)(g * HIDD + n) * IND + k] = __float2half(W[k * HIDD + n]);
        } else {
            int t = idx - CX4_TOTAL - CW_TOTAL;
            int k = t % CONCAT;
            int n = t / CONCAT;
            g_BtL[(size_t)n * CONCAT + k] = __float2half(WL[k * OUTD + n]);
        }
    }
}

// ============================================================================
// Pre-GEMM aggregation on fp16 X (fp32 accum, fp16 out).
// 64 threads per dst row (8 halfs = 16B per thread -> LDG.128 per edge);
// 2 dst rows per 128-thread block; edge loop x2 with dual accumulators.
// grid = (NN/2, GG)
// ============================================================================
__device__ __forceinline__ void h8_fma(float* acc, uint4 v, float s) {
    __half2 h0 = *(__half2*)&v.x, h1 = *(__half2*)&v.y;
    __half2 h2 = *(__half2*)&v.z, h3 = *(__half2*)&v.w;
    float2 f0 = __half22float2(h0), f1 = __half22float2(h1);
    float2 f2 = __half22float2(h2), f3 = __half22float2(h3);
    acc[0] += f0.x * s; acc[1] += f0.y * s;
    acc[2] += f1.x * s; acc[3] += f1.y * s;
    acc[4] += f2.x * s; acc[5] += f2.y * s;
    acc[6] += f3.x * s; acc[7] += f3.y * s;
}

__global__ void __launch_bounds__(128)
agg_x_kernel() {
    int g = blockIdx.y;
    int dst = blockIdx.x * 2 + (threadIdx.x >> 6);
    int lane = threadIdx.x & 63;
    int c = lane * 8;                               // 8 halfs per thread

    int beg = g_off[g * (NN + 1) + dst];
    int end = g_off[g * (NN + 1) + dst + 1];
    const int* srcs = g_csr_src + g * EE;
    const int* dout = &DEG_OUT(g, 0);

    float acc0[8] = {0.f, 0.f, 0.f, 0.f, 0.f, 0.f, 0.f, 0.f};
    float acc1[8] = {0.f, 0.f, 0.f, 0.f, 0.f, 0.f, 0.f, 0.f};
    int e = beg;
    for (; e + 1 < end; e += 2) {
        int s0 = srcs[e], s1 = srcs[e + 1];
        int d0 = dout[s0], d1 = dout[s1];
        float so0 = rsqrtf((float)(d0 > 1 ? d0 : 1));
        float so1 = rsqrtf((float)(d1 > 1 ? d1 : 1));
        uint4 v0 = *(const uint4*)(g_X16 + (size_t)s0 * IND + c);
        uint4 v1 = *(const uint4*)(g_X16 + (size_t)s1 * IND + c);
        h8_fma(acc0, v0, so0);
        h8_fma(acc1, v1, so1);
    }
    if (e < end) {
        int s0 = srcs[e];
        int d0 = dout[s0];
        float so0 = rsqrtf((float)(d0 > 1 ? d0 : 1));
        uint4 v0 = *(const uint4*)(g_X16 + (size_t)s0 * IND + c);
        h8_fma(acc0, v0, so0);
    }
    #pragma unroll
    for (int j = 0; j < 8; j++) acc0[j] += acc1[j];

    int di = DEG_IN(g, dst);
    float rsv = rsqrtf((float)(di > 1 ? di : 1));

    uint4 o;
    __half2* op = (__half2*)&o;
    #pragma unroll
    for (int j = 0; j < 4; j++)
        op[j] = __floats2half2_rn(acc0[2 * j] * rsv, acc0[2 * j + 1] * rsv);
    *(uint4*)(g_AX + ((size_t)g * NN + dst) * IND + c) = o;
}

// ============================================================================
// Single-pass fp16 GEMM: 128 threads, 4 warps (2x2), warp tile (BM/2) x 64.
// CTA tile BM x 128, BK=64, 3-stage cp.async pipeline, 1 barrier/chunk,
// swizzled ldmatrix, 2 CTAs/SM.
// mode 1: g=blockIdx.z; A=g_AX[g] (K=512), B=g_Bt[g]; tanh -> g_H
// mode 2: A=g_H (K=1536), B=g_BtL; +bias0 -> outp
// ============================================================================
#define NSTAGE 3

template<int BM>
__device__ __forceinline__ void prefetch_chunk(uint32_t sdst,
        const __half* __restrict__ A, const __half* __restrict__ B,
        int kc, int m0, int n0, int K, int tid) {
    const int TOT = (BM + 128) * 8;   // 16B segments
    #pragma unroll
    for (int i = tid; i < TOT; i += 128) {
        int row = i >> 3;
        int col = (i & 7) * 16;
        if (row < BM) {
            int mrow = m0 + row; if (mrow >= NN) mrow = NN - 1;  // clamped rows never stored
            uint32_t swz = ((uint32_t)(row * 128 + col)) ^ ((uint32_t)(row & 7) << 4);
            CP16(sdst + swz, (const char*)(A + (size_t)mrow * K) + kc * 128 + col);
        } else {
            int r2 = row - BM;
            uint32_t swz = ((uint32_t)(r2 * 128 + col)) ^ ((uint32_t)(r2 & 7) << 4);
            CP16(sdst + BM * 128 + swz, (const char*)(B + (size_t)(n0 + r2) * K) + kc * 128 + col);
        }
    }
}

template<int BM, int MI>
__global__ void __launch_bounds__(128, 2)
mma_gemm_kernel(float* outp, const float* __restrict__ bias0,
                const float* __restrict__ bias1, const float* __restrict__ bias2,
                int mode, int K) {
    constexpr int SBYTES = (BM + 128) * 128;
    extern __shared__ char smem_raw[];
    uint32_t sb0 = smem_to_u32(smem_raw);
    uint32_t sb = (sb0 + 1023) & ~1023u;

    int g = blockIdx.z;
    const __half *A, *B;
    const float* bias;
    if (mode == 1) {
        A = g_AX + (size_t)g * NN * IND;
        B = g_Bt + (size_t)g * HIDD * IND;
        bias = (g == 0) ? bias0 : (g == 1) ? bias1 : bias2;
    } else {
        A = g_H; B = g_BtL; bias = bias0;
    }

    int tid = threadIdx.x;
    int lane = tid & 31, wid = tid >> 5;
    int warpM = wid >> 1, warpN = wid & 1;     // 2x2 warp grid
    int n0 = blockIdx.x * 128;
    int m0 = blockIdx.y * BM;

    float acc[MI][8][4];
    #pragma unroll
    for (int i = 0; i < MI; i++)
        #pragma unroll
        for (int j = 0; j < 8; j++)
            #pragma unroll
            for (int r = 0; r < 4; r++) acc[i][j][r] = 0.f;

    int aRow = warpM * (BM / 2) + (lane & 15);
    int aCol = (lane >> 4) * 16;
    int bRow = warpN * 64 + (lane & 7) + (lane >> 4) * 8;
    int bCol = ((lane >> 3) & 1) * 16;

    int nk = K >> 6;
    prefetch_chunk<BM>(sb, A, B, 0, m0, n0, K, tid);
    CP_COMMIT();
    if (nk > 1) { prefetch_chunk<BM>(sb + SBYTES, A, B, 1, m0, n0, K, tid); }
    CP_COMMIT();

    for (int kc = 0; kc < nk; kc++) {
        if (kc + 2 < nk) CP_WAIT(1);
        else             CP_WAIT(0);
        __syncthreads();
        if (kc + 2 < nk) {
            prefetch_chunk<BM>(sb + ((kc + 2) % NSTAGE) * SBYTES, A, B, kc + 2, m0, n0, K, tid);
            CP_COMMIT();
        }

        uint32_t abase = sb + (kc % NSTAGE) * SBYTES;
        uint32_t bbase = abase + BM * 128;

        #pragma unroll
        for (int q = 0; q < 4; q++) {
            uint32_t bh[4][4];
            #pragma unroll
            for (int gi = 0; gi < 4; gi++) {
                int r = bRow + gi * 16;
                uint32_t off = ((uint32_t)(r * 128 + q * 32 + bCol)) ^ ((uint32_t)(r & 7) << 4);
                LDSM_X4(bh[gi][0], bh[gi][1], bh[gi][2], bh[gi][3], bbase + off);
            }
            #pragma unroll
            for (int mi = 0; mi < MI; mi++) {
                int r = aRow + mi * 16;
                uint32_t off = ((uint32_t)(r * 128 + q * 32 + aCol)) ^ ((uint32_t)(r & 7) << 4);
                uint32_t ah[4];
                LDSM_X4(ah[0], ah[1], ah[2], ah[3], abase + off);
                #pragma unroll
                for (int nj = 0; nj < 8; nj++) {
                    uint32_t bf[2] = { bh[nj >> 1][(nj & 1) * 2], bh[nj >> 1][(nj & 1) * 2 + 1] };
                    MMA_F16(acc[mi][nj], ah, bf);
                }
            }
        }
    }

    float alpha = (mode == 1) ? g_alpha[g] : 0.f;

    #pragma unroll
    for (int mi = 0; mi < MI; mi++) {
        #pragma unroll
        for (int nj = 0; nj < 8; nj++) {
            int m = m0 + warpM * (BM / 2) + mi * 16 + (lane >> 2);
            int n = n0 + warpN * 64 + nj * 8 + (lane & 3) * 2;
            float c0 = acc[mi][nj][0], c1 = acc[mi][nj][1];
            float c2 = acc[mi][nj][2], c3 = acc[mi][nj][3];
            float bx = bias[n], by = bias[n + 1];
            if (mode == 1) {
                size_t coln = (size_t)g * HIDD + n;
                if (m < NN) {
                    float h0 = fast_tanh(alpha * (c0 + bx));
                    float h1 = fast_tanh(alpha * (c1 + by));
                    *(__half2*)(g_H + (size_t)m * CONCAT + coln) =
                        __halves2half2(__float2half(h0), __float2half(h1));
                }
                if (m + 8 < NN) {
                    float h2 = fast_tanh(alpha * (c2 + bx));
                    float h3 = fast_tanh(alpha * (c3 + by));
                    *(__half2*)(g_H + (size_t)(m + 8) * CONCAT + coln) =
                        __halves2half2(__float2half(h2), __float2half(h3));
                }
            } else {
                if (m < NN)
                    *(float2*)(outp + (size_t)m * OUTD + n) = make_float2(c0 + bx, c1 + by);
                if (m + 8 < NN)
                    *(float2*)(outp + (size_t)(m + 8) * OUTD + n) = make_float2(c2 + bx, c3 + by);
            }
        }
    }
}

#define SMEM1 (1024 + NSTAGE * (128 + 128) * 128)   // 99328
#define SMEM2 (1024 + NSTAGE * (64 + 128) * 128)    // 74752

// ============================================================================
// Launch — R14 structure + wide-load aggregation.
// ============================================================================
extern "C" void kernel_launch(void* const* d_in, const int* in_sizes, int n_in,
                              void* d_out, int out_size) {
    const float* x = nullptr;
    const int*   e[GG]  = {nullptr, nullptr, nullptr};
    const float* W[GG]  = {nullptr, nullptr, nullptr};
    const float* b[GG]  = {nullptr, nullptr, nullptr};
    const float* alphas = nullptr;
    const float* W_lin  = nullptr;
    const float* b_lin  = nullptr;
    int ne = 0, nw = 0, nb = 0;

    for (int i = 0; i < n_in; i++) {
        int sz = in_sizes[i];
        if      (sz == NN * IND)      x = (const float*)d_in[i];
        else if (sz == 2 * EE)        { if (ne < GG) e[ne++] = (const int*)d_in[i]; }
        else if (sz == IND * HIDD)    { if (nw < GG) W[nw++] = (const float*)d_in[i]; }
        else if (sz == HIDD)          { if (nb < GG) b[nb++] = (const float*)d_in[i]; }
        else if (sz == GG)            alphas = (const float*)d_in[i];
        else if (sz == CONCAT * OUTD) W_lin = (const float*)d_in[i];
        else if (sz == OUTD)          b_lin = (const float*)d_in[i];
    }
    float* out = (float*)d_out;

    static cudaStream_t s2 = nullptr;
    static cudaEvent_t ev_fork = nullptr, ev_conv = nullptr;
    if (!s2) {
        cudaStreamCreateWithFlags(&s2, cudaStreamNonBlocking);
        cudaEventCreateWithFlags(&ev_fork, cudaEventDisableTiming);
        cudaEventCreateWithFlags(&ev_conv, cudaEventDisableTiming);
    }

    cudaFuncSetAttribute((const void*)mma_gemm_kernel<128, 4>,
                         cudaFuncAttributeMaxDynamicSharedMemorySize, SMEM1);
    cudaFuncSetAttribute((const void*)mma_gemm_kernel<64, 2>,
                         cudaFuncAttributeMaxDynamicSharedMemorySize, SMEM2);

    void* degp = nullptr;
    cudaGetSymbolAddress(&degp, g_deg);
    cudaMemsetAsync(degp, 0, sizeof(int) * 2 * GG * NN, 0);

    // Fork conversions onto s2 (overlap with CSR build on s0)
    cudaEventRecord(ev_fork, 0);
    cudaStreamWaitEvent(s2, ev_fork, 0);
    conv_all_kernel<<<1184, 256, 0, s2>>>(x, W[0], W[1], W[2], W_lin);
    cudaEventRecord(ev_conv, s2);

    hist_kernel<<<(GG * EE + 255) / 256, 256>>>(e[0], e[1], e[2]);
    dim3 gridS(NTILES, GG);
    scanA_kernel<<<gridS, 1024>>>();
    scanC_kernel<<<gridS, 1024>>>(alphas);
    fill_kernel<<<(GG * EE + 255) / 256, 256>>>(e[0], e[1], e[2]);

    // Join: agg needs CSR (s0, ordered) + X16 (s2)
    cudaStreamWaitEvent(0, ev_conv, 0);

    dim3 gridA(NN / 2, GG);          // 2 dst rows per block
    agg_x_kernel<<<gridA, 128>>>();

    // GEMM1: fused, all 3 branches, BM=128
    int mtiles1 = (NN + 127) / 128;          // 235
    dim3 grid1(HIDD / 128, mtiles1, GG);     // 4 x 235 x 3
    mma_gemm_kernel<128, 4><<<grid1, 128, SMEM1>>>(nullptr, b[0], b[1], b[2], 1, IND);

    // GEMM2: BM=64 (938 CTAs)
    int mtiles2 = (NN + 63) / 64;            // 469
    dim3 grid2(OUTD / 128, mtiles2, 1);      // 2 x 469
    mma_gemm_kernel<64, 2><<<grid2, 128, SMEM2>>>(out, b_lin, nullptr, nullptr, 2, CONCAT);
}